// round 12
// baseline (speedup 1.0000x reference)
#include <cuda_runtime.h>
#include <cstdint>

#define HH 128
#define WW 128
#define CHN 64
#define OCH 64
#define BATCH 4

#define CC 8             // channels per chunk (8 chunks)
#define YP 136           // y row pitch (floats); 136 % 32 == 8 -> conflict-free a-LDS
#define YOFF 4           // left pad: px p lives at row offset 4+p (float4-aligned)

#define YBUF_FLOATS (4 * CC * YP)           // 4352 per buffer
#define W_FLOAT2    (9 * 256)               // 2304 float2 per chunk (all 9 taps)
#define OFF_Y  0
#define OFF_W  (2 * YBUF_FLOATS)            // 8704 (byte 34816, 16B aligned)
#define OFF_FA (OFF_W + 2 * W_FLOAT2 * 2)   // 17920
#define OFF_BI (OFF_FA + 4 * YP)            // 18464
#define SMEM_FLOATS (OFF_BI + 64)
#define SMEM_BYTES  (SMEM_FLOATS * 4)       // 74112 B -> 2 CTAs/SM

__device__ __forceinline__ float to_tf32(float x) {
    float r; asm("cvt.rn.tf32.f32 %0, %1;" : "=f"(r) : "f"(x)); return r;
}

__device__ __forceinline__ void mma_tf32(float* d, const uint32_t* a, uint32_t b0, uint32_t b1) {
    asm volatile(
        "mma.sync.aligned.m16n8k8.row.col.f32.tf32.tf32.f32 "
        "{%0,%1,%2,%3}, {%4,%5,%6,%7}, {%8,%9}, {%0,%1,%2,%3};\n"
        : "+f"(d[0]), "+f"(d[1]), "+f"(d[2]), "+f"(d[3])
        : "r"(a[0]), "r"(a[1]), "r"(a[2]), "r"(a[3]), "r"(b0), "r"(b1));
}

__device__ __forceinline__ void cp_async16(uint32_t s_addr, const void* g) {
    asm volatile("cp.async.cg.shared.global [%0], [%1], 16;" :: "r"(s_addr), "l"(g));
}

// ---- prepacked k-paired weights, per 8-channel chunk:
// g_w5[ch][t][j*32 + lane] (lane = 4*qid+tq) =
//   ( tf32(W[n=j*8+qid][ch*8+tq][t]), tf32(W[n][ch*8+tq+4][t]) )
// Read: bv[j] = w2_s[t*256 + j*32 + lane] -> consecutive LDS.64, conflict-free.
__device__ __align__(16) float2 g_w5[8 * W_FLOAT2];

__global__ void wt_prepack(const float* __restrict__ w) {
    int i = blockIdx.x * 256 + threadIdx.x;
    if (i >= 8 * W_FLOAT2) return;
    int tq  = i & 3;
    int qid = (i >> 2) & 7;
    int j   = (i >> 5) & 7;
    int t   = (i >> 8) % 9;
    int ch  = (i >> 8) / 9;
    int n   = j * 8 + qid;
    int c0  = ch * CC + tq;
    float v0 = w[(n * CHN + c0) * 9 + t];
    float v1 = w[(n * CHN + c0 + 4) * 9 + t];
    g_w5[i] = make_float2(to_tf32(v0), to_tf32(v1));
}

// ============================ main kernel ============================
// CTA = (batch, row-pair). M = 256 px, N = 64, K = 576 in 8 chunks of 8 ch.
// Software pipeline: chunk ch+1's weights via cp.async and x via register
// staging are in flight during chunk ch's barrier-free 9-tap MMA stream.

__global__ __launch_bounds__(256, 2)
void conv_mma(const float* __restrict__ x,
              const float* __restrict__ alpha,
              const float* __restrict__ bias,
              const float* __restrict__ pa,
              const float* __restrict__ pb,
              const float* __restrict__ pc,
              float* __restrict__ out)
{
    extern __shared__ float sm[];
    float*  y_s  = sm + OFF_Y;              // [2 buf][4 ir][8 c][YP]
    float2* w2_s = (float2*)(sm + OFF_W);   // [2 buf][9 t][256]
    float*  fa_s = sm + OFF_FA;             // [4 ir][YP]
    float*  bi_s = sm + OFF_BI;

    const int tid  = threadIdx.x;
    const int warp = tid >> 5;
    const int lane = tid & 31;
    const int qid  = lane >> 2;
    const int tq   = lane & 3;

    const int rp = blockIdx.x;
    const int b  = blockIdx.y;
    const int r0 = 2 * rp;

    const int lr  = warp >> 2;          // output row within pair
    const int px0 = (warp & 3) * 32;    // pixel block

    const uint32_t w_s_addr = (uint32_t)__cvta_generic_to_shared(w2_s);

    // staging-geometry for this thread's 4 float4 (chunk y tile = 1024 float4)
    int s_ir[4], s_c[4], s_px[4];
    #pragma unroll
    for (int q = 0; q < 4; q++) {
        int idx = tid + q * 256;
        s_px[q] = (idx & 31) * 4;
        s_ir[q] = idx >> 8;
        s_c[q]  = (idx >> 5) & 7;
    }

    // ---- f(alpha), bias, y pad-zeros (static; written once)
    {
        const float A = __ldg(pa), Bq = __ldg(pb), Cq = __ldg(pc);
        const float* ap = alpha + b * HH * WW;
        for (int i = tid; i < 4 * 128; i += 256) {
            int ir = i >> 7, px = i & 127;
            int gy = r0 - 1 + ir;
            float v = 0.0f;
            if ((unsigned)gy < HH) {
                float t = __ldg(ap + gy * WW + px);
                v = (A * t + Bq) * t + Cq;
            }
            fa_s[ir * YP + YOFF + px] = v;
        }
        for (int i = tid; i < 64 * 8; i += 256) {   // pads in BOTH y buffers
            int r = i >> 3, o = i & 7;
            y_s[r * YP + (o < 4 ? o : 128 + o)] = 0.0f;
        }
        if (tid < 64) bi_s[tid] = __ldg(bias + tid);
    }

    // ---- prologue: chunk 0 weights (cp.async) + x (regs -> smem)
    {
        const char* src = (const char*)g_w5;
        #pragma unroll
        for (int i = 0; i < 5; i++) {
            int seg = tid + i * 256;
            if (seg < 1152) cp_async16(w_s_addr + seg * 16, src + seg * 16);
        }
        asm volatile("cp.async.commit_group;" ::: "memory");

        float4 xs[4];
        #pragma unroll
        for (int q = 0; q < 4; q++) {
            int gy = r0 - 1 + s_ir[q];
            xs[q] = make_float4(0.f, 0.f, 0.f, 0.f);
            if ((unsigned)gy < HH)
                xs[q] = *(const float4*)(x + (((b * CHN + s_c[q]) * HH) + gy) * WW + s_px[q]);
        }
        #pragma unroll
        for (int q = 0; q < 4; q++) {
            float4 f = *(const float4*)(fa_s + s_ir[q] * YP + YOFF + s_px[q]);
            float4 yv = make_float4(to_tf32(xs[q].x * f.x), to_tf32(xs[q].y * f.y),
                                    to_tf32(xs[q].z * f.z), to_tf32(xs[q].w * f.w));
            *(float4*)(y_s + (s_ir[q] * CC + s_c[q]) * YP + YOFF + s_px[q]) = yv;
        }
    }

    float d[2][8][4];
    #pragma unroll
    for (int mi = 0; mi < 2; mi++)
        #pragma unroll
        for (int j = 0; j < 8; j++)
            #pragma unroll
            for (int r = 0; r < 4; r++) d[mi][j][r] = 0.0f;

    #pragma unroll 1
    for (int ch = 0; ch < 8; ch++) {
        asm volatile("cp.async.wait_group 0;" ::: "memory");   // this chunk's weights
        __syncthreads();                                       // + this chunk's y STS

        const int cur = ch & 1;
        const int nxt = cur ^ 1;

        float4 xs[4];
        if (ch < 7) {
            // prefetch chunk ch+1: weights via cp.async, x into regs
            const char* src = (const char*)(g_w5 + (ch + 1) * W_FLOAT2);
            #pragma unroll
            for (int i = 0; i < 5; i++) {
                int seg = tid + i * 256;
                if (seg < 1152) cp_async16(w_s_addr + nxt * 18432 + seg * 16, src + seg * 16);
            }
            asm volatile("cp.async.commit_group;" ::: "memory");

            #pragma unroll
            for (int q = 0; q < 4; q++) {
                int gy = r0 - 1 + s_ir[q];
                xs[q] = make_float4(0.f, 0.f, 0.f, 0.f);
                if ((unsigned)gy < HH)
                    xs[q] = *(const float4*)(x + (((b * CHN + (ch + 1) * CC + s_c[q]) * HH) + gy) * WW + s_px[q]);
            }
        } else {
            asm volatile("cp.async.commit_group;" ::: "memory");  // keep wait_group balanced
        }

        // ---- 9 taps on current buffers, barrier-free (LDG latency hides here)
        const float*  yb = y_s + cur * YBUF_FLOATS;
        const float2* wb = w2_s + cur * W_FLOAT2 + lane;
        #pragma unroll 1
        for (int t = 0; t < 9; t++) {
            const int kt = t / 3, lt = t - 3 * kt;
            const float*  arow = yb + ((lr + kt) * CC + tq) * YP + YOFF + px0 + lt - 1 + qid;
            const float2* wq = wb + t * 256;

            float2 bv[8];
            #pragma unroll
            for (int j = 0; j < 8; j++) bv[j] = wq[j * 32];

            uint32_t a[2][4];
            #pragma unroll
            for (int mi = 0; mi < 2; mi++) {
                const float* p = arow + mi * 16;
                a[mi][0] = __float_as_uint(p[0]);            // (m,   k)
                a[mi][1] = __float_as_uint(p[8]);            // (m+8, k)
                a[mi][2] = __float_as_uint(p[4 * YP]);       // (m,   k+4)
                a[mi][3] = __float_as_uint(p[4 * YP + 8]);   // (m+8, k+4)
            }
            #pragma unroll
            for (int mi = 0; mi < 2; mi++)
                #pragma unroll
                for (int j = 0; j < 8; j++)
                    mma_tf32(d[mi][j], a[mi],
                             __float_as_uint(bv[j].x), __float_as_uint(bv[j].y));
        }

        // ---- land chunk ch+1's y into the next buffer
        if (ch < 7) {
            #pragma unroll
            for (int q = 0; q < 4; q++) {
                float4 f = *(const float4*)(fa_s + s_ir[q] * YP + YOFF + s_px[q]);
                float4 yv = make_float4(to_tf32(xs[q].x * f.x), to_tf32(xs[q].y * f.y),
                                        to_tf32(xs[q].z * f.z), to_tf32(xs[q].w * f.w));
                *(float4*)(y_s + nxt * YBUF_FLOATS + (s_ir[q] * CC + s_c[q]) * YP + YOFF + s_px[q]) = yv;
            }
        }
    }

    // ---- epilogue (verified fragment map)
    const int imgrow = r0 + lr;
    #pragma unroll
    for (int j = 0; j < 8; j++) {
        const int o0 = j * 8 + 2 * tq;
        const float b0v = bi_s[o0], b1v = bi_s[o0 + 1];
        float* p0 = out + (((b * OCH + o0) * HH) + imgrow) * WW;
        #pragma unroll
        for (int mi = 0; mi < 2; mi++) {
            const int px = px0 + mi * 16 + qid;
            p0[px]               = d[mi][j][0] + b0v;
            p0[HH * WW + px]     = d[mi][j][1] + b1v;
            p0[px + 8]           = d[mi][j][2] + b0v;
            p0[HH * WW + px + 8] = d[mi][j][3] + b1v;
        }
    }
}

// ============================ launch ============================
extern "C" void kernel_launch(void* const* d_in, const int* in_sizes, int n_in,
                              void* d_out, int out_size)
{
    const float* x     = (const float*)d_in[0];
    const float* alpha = (const float*)d_in[1];
    const float* wgt   = (const float*)d_in[2];
    const float* bias  = (const float*)d_in[3];
    const float* pa    = (const float*)d_in[4];
    const float* pb    = (const float*)d_in[5];
    const float* pc    = (const float*)d_in[6];
    float* out = (float*)d_out;

    wt_prepack<<<(8 * W_FLOAT2 + 255) / 256, 256>>>(wgt);

    cudaFuncSetAttribute(conv_mma,
                         cudaFuncAttributeMaxDynamicSharedMemorySize, SMEM_BYTES);
    dim3 grid(HH / 2, BATCH);   // 64 x 4 = 256 CTAs, single wave at 2 CTA/SM
    conv_mma<<<grid, 256, SMEM_BYTES>>>(x, alpha, bias, pa, pb, pc, out);
}

// round 15
// speedup vs baseline: 1.6319x; 1.6319x over previous
#include <cuda_runtime.h>
#include <cuda_fp16.h>
#include <cstdint>

#define HH 128
#define WW 128
#define CHN 64
#define OCH 64
#define BATCH 4

#define CC 16            // channels per chunk (4 chunks), K=16 per MMA
#define Y2P 136          // y u32 pitch; 136 % 32 == 8 -> conflict-free a-LDS
#define YOFF 4           // left pad: px p at row offset 4+p (16B-aligned stores)

#define Y_U32   (32 * Y2P)                  // 4352  (32 rows = 4 ir x 8 cpair)
#define W_U2    2304                        // uint2 per chunk (9 taps x 256)
#define OFF_Y   0                           // bytes
#define OFF_W   (Y_U32 * 4)                 // 17408 (16B aligned)
#define OFF_FA  (OFF_W + 2 * W_U2 * 8)      // 54272
#define OFF_BI  (OFF_FA + 4 * Y2P * 4)      // 56448
#define SMEM_BYTES (OFF_BI + 256)           // 56704 -> 2 CTAs/SM

__device__ __forceinline__ uint32_t pack_h2(float lo, float hi) {
    __half2 h = __floats2half2_rn(lo, hi);
    return *reinterpret_cast<uint32_t*>(&h);
}

__device__ __forceinline__ void mma_fp16(float* d, uint32_t a0, uint32_t a1,
                                         uint32_t a2, uint32_t a3,
                                         uint32_t b0, uint32_t b1) {
    asm volatile(
        "mma.sync.aligned.m16n8k16.row.col.f32.f16.f16.f32 "
        "{%0,%1,%2,%3}, {%4,%5,%6,%7}, {%8,%9}, {%0,%1,%2,%3};\n"
        : "+f"(d[0]), "+f"(d[1]), "+f"(d[2]), "+f"(d[3])
        : "r"(a0), "r"(a1), "r"(a2), "r"(a3), "r"(b0), "r"(b1));
}

__device__ __forceinline__ void cp_async16(uint32_t s_addr, const void* g) {
    asm volatile("cp.async.cg.shared.global [%0], [%1], 16;" :: "r"(s_addr), "l"(g));
}

// ---- prepacked fp16 k-paired weights, per 16-channel chunk:
// g_w6[ch][t][j*32 + lane] (lane = 4*qid+tq, n = j*8+qid) = uint2
//   .x = h2( W[n][ch*16+2tq][t],   W[n][ch*16+2tq+1][t] )   -> b0 (k, k+1)
//   .y = h2( W[n][ch*16+2tq+8][t], W[n][ch*16+2tq+9][t] )   -> b1 (k+8, k+9)
__device__ __align__(16) uint2 g_w6[4 * W_U2];

__global__ void wt_prepack(const float* __restrict__ w) {
    int i = blockIdx.x * 256 + threadIdx.x;
    if (i >= 4 * W_U2) return;
    int tq  = i & 3;
    int qid = (i >> 2) & 7;
    int j   = (i >> 5) & 7;
    int t   = (i >> 8) % 9;
    int ch  = (i >> 8) / 9;
    int n   = j * 8 + qid;
    int c0  = ch * CC + 2 * tq;
    uint2 v;
    v.x = pack_h2(w[(n * CHN + c0) * 9 + t],     w[(n * CHN + c0 + 1) * 9 + t]);
    v.y = pack_h2(w[(n * CHN + c0 + 8) * 9 + t], w[(n * CHN + c0 + 9) * 9 + t]);
    g_w6[i] = v;
}

// ============================ main kernel ============================
// CTA = (batch, row-pair). M = 256 px, N = 64, K = 576 in 4 chunks of 16 ch.
// fp16 m16n8k16: same 11-bit mantissa as tf32 (rel_err preserved) but half the
// smem bytes and half the HMMA count per MAC. 8 warps, warp tile 32px x 64o.
// y stored as f16x2 channel pairs; b as paired LDS.64. Weights double-buffered
// via cp.async; y single-buffered with one barrier pair per chunk.

__global__ __launch_bounds__(256, 2)
void conv_mma(const float* __restrict__ x,
              const float* __restrict__ alpha,
              const float* __restrict__ bias,
              const float* __restrict__ pa,
              const float* __restrict__ pb,
              const float* __restrict__ pc,
              float* __restrict__ out)
{
    extern __shared__ char smem[];
    uint32_t* y2_s = (uint32_t*)(smem + OFF_Y);   // [4 ir][8 cpair][Y2P] f16x2
    uint2*    w2_s = (uint2*)   (smem + OFF_W);   // [2 buf][9 t][256]
    float*    fa_s = (float*)   (smem + OFF_FA);  // [4 ir][Y2P]
    float*    bi_s = (float*)   (smem + OFF_BI);

    const int tid  = threadIdx.x;
    const int warp = tid >> 5;
    const int lane = tid & 31;
    const int qid  = lane >> 2;
    const int tq   = lane & 3;

    const int rp = blockIdx.x;
    const int b  = blockIdx.y;
    const int r0 = 2 * rp;

    const int lr  = warp >> 2;          // output row within pair
    const int px0 = (warp & 3) * 32;    // pixel block

    const uint32_t w_s_addr = (uint32_t)__cvta_generic_to_shared(w2_s);

    // ---- f(alpha), bias, y pad-zeros (written once; fills never touch pads)
    {
        const float A = __ldg(pa), Bq = __ldg(pb), Cq = __ldg(pc);
        const float* ap = alpha + b * HH * WW;
        for (int i = tid; i < 4 * 128; i += 256) {
            int ir = i >> 7, px = i & 127;
            int gy = r0 - 1 + ir;
            float v = 0.0f;
            if ((unsigned)gy < HH) {
                float t = __ldg(ap + gy * WW + px);
                v = (A * t + Bq) * t + Cq;
            }
            fa_s[ir * Y2P + YOFF + px] = v;
        }
        {   // zero u32 pads: offsets 0..3 and 132..135 of each of 32 rows
            int r = tid >> 3, o = tid & 7;
            y2_s[r * Y2P + (o < 4 ? o : 128 + o)] = 0u;
        }
        if (tid < 64) bi_s[tid] = __ldg(bias + tid);
    }

    // ---- prologue: chunk 0 weights via cp.async
    {
        const char* src = (const char*)g_w6;
        #pragma unroll
        for (int i = 0; i < 5; i++) {
            int seg = tid + i * 256;
            if (seg < 1152) cp_async16(w_s_addr + seg * 16, src + seg * 16);
        }
        asm volatile("cp.async.commit_group;" ::: "memory");
    }

    float d[2][8][4];
    #pragma unroll
    for (int mi = 0; mi < 2; mi++)
        #pragma unroll
        for (int j = 0; j < 8; j++)
            #pragma unroll
            for (int r = 0; r < 4; r++) d[mi][j][r] = 0.0f;

    #pragma unroll 1
    for (int ch = 0; ch < 4; ch++) {
        __syncthreads();   // pads/fa ready (ch=0); prev chunk's y readers done

        // ---- y fill: f16x2 channel pairs, premultiplied by f(alpha).
        // 1024 uint4 stores; thread q-th iter handles row r = tid>>5 + q*8? No:
        // idx = tid + q*256: row = idx>>5 (ir = row>>3, cp = row&7), px4 = (idx&31)*4.
        #pragma unroll
        for (int q = 0; q < 4; q++) {
            int idx = tid + q * 256;
            int row = idx >> 5;
            int ir  = row >> 3, cp = row & 7;
            int px4 = (idx & 31) * 4;
            int gy  = r0 - 1 + ir;
            float4 v0 = make_float4(0.f, 0.f, 0.f, 0.f);
            float4 v1 = v0;
            if ((unsigned)gy < HH) {
                const float* xp = x + (((b * CHN + ch * CC + 2 * cp) * HH) + gy) * WW + px4;
                v0 = *(const float4*)xp;
                v1 = *(const float4*)(xp + HH * WW);
            }
            float4 f = *(const float4*)(fa_s + ir * Y2P + YOFF + px4);
            uint4 s;
            s.x = pack_h2(v0.x * f.x, v1.x * f.x);
            s.y = pack_h2(v0.y * f.y, v1.y * f.y);
            s.z = pack_h2(v0.z * f.z, v1.z * f.z);
            s.w = pack_h2(v0.w * f.w, v1.w * f.w);
            *(uint4*)(y2_s + row * Y2P + YOFF + px4) = s;
        }

        asm volatile("cp.async.wait_group 0;" ::: "memory");   // this chunk's w
        __syncthreads();

        // prefetch next chunk's weights during the tap stream
        if (ch < 3) {
            const char* src = (const char*)(g_w6 + (ch + 1) * W_U2);
            uint32_t dst = w_s_addr + ((ch + 1) & 1) * (W_U2 * 8);
            #pragma unroll
            for (int i = 0; i < 5; i++) {
                int seg = tid + i * 256;
                if (seg < 1152) cp_async16(dst + seg * 16, src + seg * 16);
            }
            asm volatile("cp.async.commit_group;" ::: "memory");
        } else {
            asm volatile("cp.async.commit_group;" ::: "memory");  // balance waits
        }

        // ---- 9 taps, barrier-free
        const uint2* wb = w2_s + (ch & 1) * W_U2 + lane;
        #pragma unroll 1
        for (int t = 0; t < 9; t++) {
            const int kt = t / 3, lt = t - 3 * kt;
            const uint32_t* ar0 = y2_s + ((lr + kt) * 8 + tq) * Y2P + YOFF + px0 + lt - 1 + qid;
            const uint32_t* ar1 = ar0 + 4 * Y2P;          // channel pair tq+4 (k+8)
            const uint2* wq = wb + t * 256;

            uint2 bv[8];
            #pragma unroll
            for (int j = 0; j < 8; j++) bv[j] = wq[j * 32];   // LDS.64, conflict-free

            #pragma unroll
            for (int mi = 0; mi < 2; mi++) {
                uint32_t a0 = ar0[mi * 16];          // (m,    k0..1)
                uint32_t a1 = ar0[mi * 16 + 8];      // (m+8,  k0..1)
                uint32_t a2 = ar1[mi * 16];          // (m,    k8..9)
                uint32_t a3 = ar1[mi * 16 + 8];      // (m+8,  k8..9)
                #pragma unroll
                for (int j = 0; j < 8; j++)
                    mma_fp16(d[mi][j], a0, a1, a2, a3, bv[j].x, bv[j].y);
            }
        }
    }

    // ---- epilogue (verified fragment map: same D layout as m16n8k8)
    const int imgrow = r0 + lr;
    #pragma unroll
    for (int j = 0; j < 8; j++) {
        const int o0 = j * 8 + 2 * tq;
        const float b0v = bi_s[o0], b1v = bi_s[o0 + 1];
        float* p0 = out + (((b * OCH + o0) * HH) + imgrow) * WW;
        #pragma unroll
        for (int mi = 0; mi < 2; mi++) {
            const int px = px0 + mi * 16 + qid;
            p0[px]               = d[mi][j][0] + b0v;
            p0[HH * WW + px]     = d[mi][j][1] + b1v;
            p0[px + 8]           = d[mi][j][2] + b0v;
            p0[HH * WW + px + 8] = d[mi][j][3] + b1v;
        }
    }
}

// ============================ launch ============================
extern "C" void kernel_launch(void* const* d_in, const int* in_sizes, int n_in,
                              void* d_out, int out_size)
{
    const float* x     = (const float*)d_in[0];
    const float* alpha = (const float*)d_in[1];
    const float* wgt   = (const float*)d_in[2];
    const float* bias  = (const float*)d_in[3];
    const float* pa    = (const float*)d_in[4];
    const float* pb    = (const float*)d_in[5];
    const float* pc    = (const float*)d_in[6];
    float* out = (float*)d_out;

    wt_prepack<<<(4 * W_U2 + 255) / 256, 256>>>(wgt);

    cudaFuncSetAttribute(conv_mma,
                         cudaFuncAttributeMaxDynamicSharedMemorySize, SMEM_BYTES);
    dim3 grid(HH / 2, BATCH);   // 64 x 4 = 256 CTAs, single wave at 2 CTA/SM
    conv_mma<<<grid, 256, SMEM_BYTES>>>(x, alpha, bias, pa, pb, pc, out);
}